// round 9
// baseline (speedup 1.0000x reference)
#include <cuda_runtime.h>
#include <math.h>

typedef unsigned int u32;

// weight buffer (floats): w3+WB -> smem (3-chain reuse); rest stay GLOBAL (L2-hot)
#define FB_W3  0
#define FB_WB  2048
#define FB_SM  4096                // floats copied to smem
#define FB_W0  4096
#define FB_W1  6144
#define FB_W2  8192
#define FB_WA  10240
#define FB_WM1 12288
#define FB_WM2 16384
#define FB_WM3 20480
#define FB_TOT 28672

#define NWARP  12
#define TSTR   68
#define TFL    (16 * TSTR)          // 1088
#define OSTR   132
#define ARENA  (4 * TFL)            // 4352 floats; Yt lives in A3 column padding
#define SMEM_FLOATS (FB_SM + NWARP * ARENA)    // 4096 + 52224 = 56320
#define SMEM_BYTES  (SMEM_FLOATS * 4)          // 225280

__device__ float g_cst;
__device__ float g_wbuf[FB_TOT];

__device__ __forceinline__ u32 tf32(float f) {
    u32 u; asm("cvt.rna.tf32.f32 %0,%1;" : "=r"(u) : "f"(f)); return u;
}
__device__ __forceinline__ void split2(float x, u32& h, u32& l) {
    h = tf32(x);
    l = tf32(x - __uint_as_float(h));
}
__device__ __forceinline__ void mma_t(float* d, u32 a0, u32 a1, u32 a2, u32 a3,
                                      u32 b0, u32 b1) {
    asm("mma.sync.aligned.m16n8k8.row.col.f32.tf32.tf32.f32 "
        "{%0,%1,%2,%3},{%4,%5,%6,%7},{%8,%9},{%0,%1,%2,%3};"
        : "+f"(d[0]), "+f"(d[1]), "+f"(d[2]), "+f"(d[3])
        : "r"(a0), "r"(a1), "r"(a2), "r"(a3), "r"(b0), "r"(b1));
}

// acc[4*NT] += T[16x64] @ W(smem) ; A hi/lo-split, W fragment-linear single tf32
template<int NT>
__device__ __forceinline__ void gemm16s(float* acc, const float* T, const float* W,
                                        int r4, int m4, int lane) {
#pragma unroll
    for (int k8 = 0; k8 < 8; k8++) {
        const float* ap = T + r4 * TSTR + k8 * 8 + m4;
        u32 h0, l0, h1, l1, h2, l2, h3, l3;
        split2(ap[0], h0, l0);
        split2(ap[8 * TSTR], h1, l1);
        split2(ap[4], h2, l2);
        split2(ap[8 * TSTR + 4], h3, l3);
        const float* wp = W + k8 * NT * 64 + 2 * lane;
#pragma unroll
        for (int nt = 0; nt < NT; nt++) {
            uint2 b = *(const uint2*)(wp + nt * 64);
            mma_t(acc + 4 * nt, h0, h1, h2, h3, b.x, b.y);
            mma_t(acc + 4 * nt, l0, l1, l2, l3, b.x, b.y);
        }
    }
}

// same but W read from GLOBAL via __ldg (L2-hot)
template<int NT>
__device__ __forceinline__ void gemm16g(float* acc, const float* T, const float* W,
                                        int r4, int m4, int lane) {
#pragma unroll
    for (int k8 = 0; k8 < 8; k8++) {
        const float* ap = T + r4 * TSTR + k8 * 8 + m4;
        u32 h0, l0, h1, l1, h2, l2, h3, l3;
        split2(ap[0], h0, l0);
        split2(ap[8 * TSTR], h1, l1);
        split2(ap[4], h2, l2);
        split2(ap[8 * TSTR + 4], h3, l3);
        const float* wp = W + k8 * NT * 64 + 2 * lane;
#pragma unroll
        for (int nt = 0; nt < NT; nt++) {
            uint2 b = __ldg((const uint2*)(wp + nt * 64));
            mma_t(acc + 4 * nt, h0, h1, h2, h3, b.x, b.y);
            mma_t(acc + 4 * nt, l0, l1, l2, l3, b.x, b.y);
        }
    }
}

// ---------------- prep ----------------
__global__ void prep_kernel(const float* __restrict__ w0, const float* __restrict__ w1,
                            const float* __restrict__ w2, const float* __restrict__ w3,
                            const float* __restrict__ Wl0, const float* __restrict__ Wl1,
                            const float* __restrict__ Wm1, const float* __restrict__ Wm2,
                            const float* __restrict__ Wm3,
                            const float* __restrict__ Wf0, const float* __restrict__ Wf1) {
    if (blockIdx.x == 0) {
        const int   N = 20000;
        const float h = 24.0f / 20000.0f;
        float local = 0.0f;
        for (int i = threadIdx.x; i <= N; i += blockDim.x) {
            float z   = -12.0f + h * (float)i;
            float s   = z / (1.0f + __expf(-z));
            float phi = __expf(-0.5f * z * z) * 0.3989422804014327f;
            float f   = s * s * phi;
            if (i == 0 || i == N) f *= 0.5f;
            local += f;
        }
        __shared__ float red[256];
        red[threadIdx.x] = local;
        __syncthreads();
        for (int s = 128; s > 0; s >>= 1) {
            if (threadIdx.x < s) red[threadIdx.x] += red[threadIdx.x + s];
            __syncthreads();
        }
        if (threadIdx.x == 0) g_cst = rsqrtf(red[0] * h);
    }

    int tid = blockIdx.x * blockDim.x + threadIdx.x;
    if (tid >= FB_TOT) return;
    const float INV_S3 = 0.57735026918962576f;
    const float WSCALE = 0.125f * 0.125f * 0.17677669529663687f;

    int mbase, N;
    if (tid < FB_WM1)          { mbase = (tid / 2048) * 2048; N = 32; }
    else if (tid < FB_WM2)     { mbase = FB_WM1; N = 64; }
    else if (tid < FB_WM3)     { mbase = FB_WM2; N = 64; }
    else                       { mbase = FB_WM3; N = 128; }
    int idx = tid - mbase;
    int g = idx >> 6, pos = idx & 63, l = pos >> 1, hh = pos & 1;
    int ntn = N >> 3, k8 = g / ntn, n8 = g % ntn;
    int row = k8 * 8 + (l & 3) + 4 * hh;   // K index
    int col = n8 * 8 + (l >> 2);           // N index

    float v;
    if (tid < FB_WM1) {
        int m = tid / 2048;   // 0:w3 1:WB 2:w0 3:w1 4:w2 5:WA
        if (m == 0)      v = w3[row * 32 + col];
        else if (m == 2) v = w0[row * 32 + col];
        else if (m == 3) v = w1[row * 32 + col] * INV_S3;
        else if (m == 4) v = w2[row * 32 + col];
        else {
            const float* L = (m == 1) ? Wl1 : Wl0;
            const float* F = (m == 1) ? Wf1 : Wf0;
            float acc = 0.0f;
            for (int w = 0; w < 32; w++) acc = fmaf(L[row * 32 + w], F[w * 32 + col], acc);
            v = acc * WSCALE;
        }
    }
    else if (tid < FB_WM2)     v = Wm1[row * 64 + col] * 0.125f;
    else if (tid < FB_WM3)     v = Wm2[row * 64 + col] * 0.125f;
    else                       v = Wm3[row * 128 + col] * 0.125f;
    g_wbuf[tid] = __uint_as_float(tf32(v));
}

// ---------------- main ----------------
__global__ __launch_bounds__(32 * NWARP, 1)
void tp_mma_kernel(const float* __restrict__ x1a, const float* __restrict__ x1b,
                   const float4* __restrict__ x2, const float* __restrict__ scalars,
                   float* __restrict__ out, int nrows) {
    extern __shared__ float smem[];
    {
        const float4* src = (const float4*)g_wbuf;
        float4* dst = (float4*)smem;
        for (int i = threadIdx.x; i < FB_SM / 4; i += 32 * NWARP) dst[i] = src[i];
    }
    __syncthreads();
    const float cst = g_cst;
    const float* w0g  = g_wbuf + FB_W0;
    const float* w1g  = g_wbuf + FB_W1;
    const float* w2g  = g_wbuf + FB_W2;
    const float* wag  = g_wbuf + FB_WA;
    const float* wm1g = g_wbuf + FB_WM1;
    const float* wm2g = g_wbuf + FB_WM2;
    const float* wm3g = g_wbuf + FB_WM3;

    const int lane = threadIdx.x & 31, wid = threadIdx.x >> 5;
    const int r4 = lane >> 2, m4 = lane & 3;

    float* A0 = smem + FB_SM + wid * ARENA;
    float* A1 = A0 + TFL;
    float* A2 = A1 + TFL;
    float* A3 = A2 + TFL;
    // Yt lives in A3 column padding: row rr -> A3[rr*TSTR + 64 .. 68)

    const int gw = blockIdx.x * NWARP + wid, gwn = gridDim.x * NWARP;
    const int ntiles = nrows >> 4;

    for (int t = gw; t < ntiles; t += gwn) {
        const int base = t * 16;

        // ---- stage scalars (fp32) + y (into A3 padding) ----
#pragma unroll
        for (int j = 0; j < 8; j++) {
            int row = r4 + 8 * (j & 1), f4 = m4 + 4 * (j >> 1);
            *(float4*)&A0[row * TSTR + 4 * f4] =
                ((const float4*)scalars)[(base + row) * 16 + f4];
        }
        if (lane < 16) *(float4*)&A3[lane * TSTR + 64] = x2[base + lane];
        __syncwarp();

        // ---- MLP GEMM1 -> silu -> GEMM2 -> silu -> GEMM3 (weights via L2) ----
        float h[32];
#pragma unroll
        for (int i = 0; i < 32; i++) h[i] = 0.f;
        gemm16g<8>(h, A0, wm1g, r4, m4, lane);
        __syncwarp();
#pragma unroll
        for (int nt = 0; nt < 8; nt++) {
            float a = h[4 * nt],     b = h[4 * nt + 1];
            float c = h[4 * nt + 2], d = h[4 * nt + 3];
            float2 lo = {cst * a / (1.f + __expf(-a)), cst * b / (1.f + __expf(-b))};
            float2 hi = {cst * c / (1.f + __expf(-c)), cst * d / (1.f + __expf(-d))};
            *(float2*)&A0[r4 * TSTR + nt * 8 + 2 * m4]       = lo;
            *(float2*)&A0[(r4 + 8) * TSTR + nt * 8 + 2 * m4] = hi;
        }
        __syncwarp();
#pragma unroll
        for (int i = 0; i < 32; i++) h[i] = 0.f;
        gemm16g<8>(h, A0, wm2g, r4, m4, lane);
        __syncwarp();
#pragma unroll
        for (int nt = 0; nt < 8; nt++) {
            float a = h[4 * nt],     b = h[4 * nt + 1];
            float c = h[4 * nt + 2], d = h[4 * nt + 3];
            float2 lo = {cst * a / (1.f + __expf(-a)), cst * b / (1.f + __expf(-b))};
            float2 hi = {cst * c / (1.f + __expf(-c)), cst * d / (1.f + __expf(-d))};
            *(float2*)&A0[r4 * TSTR + nt * 8 + 2 * m4]       = lo;
            *(float2*)&A0[(r4 + 8) * TSTR + nt * 8 + 2 * m4] = hi;
        }
        __syncwarp();
        float wt[64];
#pragma unroll
        for (int i = 0; i < 64; i++) wt[i] = 0.f;
        gemm16g<16>(wt, A0, wm3g, r4, m4, lane);
        __syncwarp();

        // ---- stage x1 -> s0 (A0), s1k (A1..A3), fp32 ----
        for (int rr = 0; rr < 16; rr++) {
            float4 va = ((const float4*)x1a)[(base + rr) * 32 + lane];
            float4 vb = ((const float4*)x1b)[(base + rr) * 32 + lane];
            if (lane < 8) {
                *(float4*)&A0[rr * TSTR + 4 * lane]      = va;
                *(float4*)&A0[rr * TSTR + 32 + 4 * lane] = vb;
            } else {
                int f = 4 * lane - 32;
                float av[4] = {va.x, va.y, va.z, va.w};
                float bv[4] = {vb.x, vb.y, vb.z, vb.w};
#pragma unroll
                for (int q = 0; q < 4; q++) {
                    int u = (f + q) / 3, k = (f + q) % 3;
                    float* Tk = (k == 0) ? A1 : ((k == 1) ? A2 : A3);
                    Tk[rr * TSTR + u]      = av[q];
                    Tk[rr * TSTR + 32 + u] = bv[q];
                }
            }
        }
        __syncwarp();

        const float y0A = A3[r4 * TSTR + 64],       y0B = A3[(r4 + 8) * TSTR + 64];
        const float yA1 = A3[r4 * TSTR + 65],       yB1 = A3[(r4 + 8) * TSTR + 65];
        const float yA2 = A3[r4 * TSTR + 66],       yB2 = A3[(r4 + 8) * TSTR + 66];
        const float yA3 = A3[r4 * TSTR + 67],       yB3 = A3[(r4 + 8) * TSTR + 67];

        // ---- G4/G5: R0 = s0@w0, Pp = s0@w2 (shared A frags; weights via L2) ----
        float R0[16], Pp[16], R1[16];
#pragma unroll
        for (int i = 0; i < 16; i++) { R0[i] = 0.f; Pp[i] = 0.f; R1[i] = 0.f; }
#pragma unroll
        for (int k8 = 0; k8 < 8; k8++) {
            const float* ap = A0 + r4 * TSTR + k8 * 8 + m4;
            u32 h0, l0, h1, l1, h2, l2, h3, l3;
            split2(ap[0], h0, l0);
            split2(ap[8 * TSTR], h1, l1);
            split2(ap[4], h2, l2);
            split2(ap[8 * TSTR + 4], h3, l3);
            const float* w0p = w0g + k8 * 4 * 64 + 2 * lane;
            const float* w2p = w2g + k8 * 4 * 64 + 2 * lane;
#pragma unroll
            for (int nt = 0; nt < 4; nt++) {
                uint2 b0 = __ldg((const uint2*)(w0p + nt * 64));
                mma_t(R0 + 4 * nt, h0, h1, h2, h3, b0.x, b0.y);
                mma_t(R0 + 4 * nt, l0, l1, l2, l3, b0.x, b0.y);
                uint2 b2 = __ldg((const uint2*)(w2p + nt * 64));
                mma_t(Pp + 4 * nt, h0, h1, h2, h3, b2.x, b2.y);
                mma_t(Pp + 4 * nt, l0, l1, l2, l3, b2.x, b2.y);
            }
        }

        // ---- G6: R1 = t1@w1, t1 frags built on the fly (w1 via L2) ----
#pragma unroll
        for (int k8 = 0; k8 < 8; k8++) {
            int o = r4 * TSTR + k8 * 8 + m4;
            float t0 = A1[o] * yA1 + A2[o] * yA2 + A3[o] * yA3;
            float t2 = A1[o + 4] * yA1 + A2[o + 4] * yA2 + A3[o + 4] * yA3;
            float t1v = A1[o + 8 * TSTR] * yB1 + A2[o + 8 * TSTR] * yB2 + A3[o + 8 * TSTR] * yB3;
            float t3 = A1[o + 8 * TSTR + 4] * yB1 + A2[o + 8 * TSTR + 4] * yB2 + A3[o + 8 * TSTR + 4] * yB3;
            u32 h0, l0, h1, l1, h2, l2, h3, l3;
            split2(t0, h0, l0); split2(t1v, h1, l1);
            split2(t2, h2, l2); split2(t3, h3, l3);
            const float* w1p = w1g + k8 * 4 * 64 + 2 * lane;
#pragma unroll
            for (int nt = 0; nt < 4; nt++) {
                uint2 b = __ldg((const uint2*)(w1p + nt * 64));
                mma_t(R1 + 4 * nt, h0, h1, h2, h3, b.x, b.y);
                mma_t(R1 + 4 * nt, l0, l1, l2, l3, b.x, b.y);
            }
        }
        __syncwarp();   // s0 reads done -> overlay m0 on A0

        // ---- m0 build -> A0 ----
#pragma unroll
        for (int nt = 0; nt < 4; nt++) {
            A0[r4 * TSTR + nt * 8 + 2 * m4]           = y0A * R0[4 * nt]     * wt[4 * nt];
            A0[r4 * TSTR + nt * 8 + 2 * m4 + 1]       = y0A * R0[4 * nt + 1] * wt[4 * nt + 1];
            A0[(r4 + 8) * TSTR + nt * 8 + 2 * m4]     = y0B * R0[4 * nt + 2] * wt[4 * nt + 2];
            A0[(r4 + 8) * TSTR + nt * 8 + 2 * m4 + 1] = y0B * R0[4 * nt + 3] * wt[4 * nt + 3];
            int wi = 4 * (nt + 4);
            A0[r4 * TSTR + 32 + nt * 8 + 2 * m4]           = R1[4 * nt]     * wt[wi];
            A0[r4 * TSTR + 32 + nt * 8 + 2 * m4 + 1]       = R1[4 * nt + 1] * wt[wi + 1];
            A0[(r4 + 8) * TSTR + 32 + nt * 8 + 2 * m4]     = R1[4 * nt + 2] * wt[wi + 2];
            A0[(r4 + 8) * TSTR + 32 + nt * 8 + 2 * m4 + 1] = R1[4 * nt + 3] * wt[wi + 3];
        }

        // ---- G7: Qk = s1k@w3 (smem; B shared across 3 chains) ----
        float Q[48];
#pragma unroll
        for (int i = 0; i < 48; i++) Q[i] = 0.f;
#pragma unroll
        for (int k8 = 0; k8 < 8; k8++) {
            u32 H[3][4], L[3][4];
#pragma unroll
            for (int k = 0; k < 3; k++) {
                const float* Tk = (k == 0) ? A1 : ((k == 1) ? A2 : A3);
                int o = r4 * TSTR + k8 * 8 + m4;
                split2(Tk[o], H[k][0], L[k][0]);
                split2(Tk[o + 8 * TSTR], H[k][1], L[k][1]);
                split2(Tk[o + 4], H[k][2], L[k][2]);
                split2(Tk[o + 8 * TSTR + 4], H[k][3], L[k][3]);
            }
            const float* w3p = smem + FB_W3 + k8 * 4 * 64 + 2 * lane;
#pragma unroll
            for (int nt = 0; nt < 4; nt++) {
                uint2 b = *(const uint2*)(w3p + nt * 64);
#pragma unroll
                for (int k = 0; k < 3; k++) {
                    mma_t(Q + 16 * k + 4 * nt, H[k][0], H[k][1], H[k][2], H[k][3], b.x, b.y);
                    mma_t(Q + 16 * k + 4 * nt, L[k][0], L[k][1], L[k][2], L[k][3], b.x, b.y);
                }
            }
        }
        __syncwarp();   // s1 reads done -> overlay m1k

        // ---- m1k build -> A1..A3 ----
#pragma unroll
        for (int k = 0; k < 3; k++) {
            float* Tk = (k == 0) ? A1 : ((k == 1) ? A2 : A3);
            float ykA = (k == 0) ? yA1 : ((k == 1) ? yA2 : yA3);
            float ykB = (k == 0) ? yB1 : ((k == 1) ? yB2 : yB3);
#pragma unroll
            for (int nt = 0; nt < 4; nt++) {
                int wi = 4 * (nt + 8), wj = 4 * (nt + 12);
                Tk[r4 * TSTR + nt * 8 + 2 * m4]           = ykA * Pp[4 * nt]     * wt[wi];
                Tk[r4 * TSTR + nt * 8 + 2 * m4 + 1]       = ykA * Pp[4 * nt + 1] * wt[wi + 1];
                Tk[(r4 + 8) * TSTR + nt * 8 + 2 * m4]     = ykB * Pp[4 * nt + 2] * wt[wi + 2];
                Tk[(r4 + 8) * TSTR + nt * 8 + 2 * m4 + 1] = ykB * Pp[4 * nt + 3] * wt[wi + 3];
                Tk[r4 * TSTR + 32 + nt * 8 + 2 * m4]           = y0A * Q[16 * k + 4 * nt]     * wt[wj];
                Tk[r4 * TSTR + 32 + nt * 8 + 2 * m4 + 1]       = y0A * Q[16 * k + 4 * nt + 1] * wt[wj + 1];
                Tk[(r4 + 8) * TSTR + 32 + nt * 8 + 2 * m4]     = y0B * Q[16 * k + 4 * nt + 2] * wt[wj + 2];
                Tk[(r4 + 8) * TSTR + 32 + nt * 8 + 2 * m4 + 1] = y0B * Q[16 * k + 4 * nt + 3] * wt[wj + 3];
            }
        }
        __syncwarp();

        // ---- G8: O0 = m0@WA (L2) ; G9: Ok = m1k@WB (smem, B shared) ----
        float O0[16];
#pragma unroll
        for (int i = 0; i < 16; i++) O0[i] = 0.f;
        gemm16g<4>(O0, A0, wag, r4, m4, lane);

        float O[48];
#pragma unroll
        for (int i = 0; i < 48; i++) O[i] = 0.f;
#pragma unroll
        for (int k8 = 0; k8 < 8; k8++) {
            u32 H[3][4], L[3][4];
#pragma unroll
            for (int k = 0; k < 3; k++) {
                const float* Tk = (k == 0) ? A1 : ((k == 1) ? A2 : A3);
                int o = r4 * TSTR + k8 * 8 + m4;
                split2(Tk[o], H[k][0], L[k][0]);
                split2(Tk[o + 8 * TSTR], H[k][1], L[k][1]);
                split2(Tk[o + 4], H[k][2], L[k][2]);
                split2(Tk[o + 8 * TSTR + 4], H[k][3], L[k][3]);
            }
            const float* wbp = smem + FB_WB + k8 * 4 * 64 + 2 * lane;
#pragma unroll
            for (int nt = 0; nt < 4; nt++) {
                uint2 b = *(const uint2*)(wbp + nt * 64);
#pragma unroll
                for (int k = 0; k < 3; k++) {
                    mma_t(O + 16 * k + 4 * nt, H[k][0], H[k][1], H[k][2], H[k][3], b.x, b.y);
                    mma_t(O + 16 * k + 4 * nt, L[k][0], L[k][1], L[k][2], L[k][3], b.x, b.y);
                }
            }
        }
        __syncwarp();   // m reads done -> overlay out staging on A0/A1

        // ---- stage outputs (OB = A0, stride OSTR) ----
        float* OB = A0;
#pragma unroll
        for (int nt = 0; nt < 4; nt++) {
            int u = nt * 8 + 2 * m4;
            OB[r4 * OSTR + u]           = O0[4 * nt];
            OB[r4 * OSTR + u + 1]       = O0[4 * nt + 1];
            OB[(r4 + 8) * OSTR + u]     = O0[4 * nt + 2];
            OB[(r4 + 8) * OSTR + u + 1] = O0[4 * nt + 3];
#pragma unroll
            for (int k = 0; k < 3; k++) {
                int c = 32 + 3 * u + k;
                OB[r4 * OSTR + c]           = O[16 * k + 4 * nt];
                OB[r4 * OSTR + c + 3]       = O[16 * k + 4 * nt + 1];
                OB[(r4 + 8) * OSTR + c]     = O[16 * k + 4 * nt + 2];
                OB[(r4 + 8) * OSTR + c + 3] = O[16 * k + 4 * nt + 3];
            }
        }
        __syncwarp();
#pragma unroll
        for (int rr = 0; rr < 16; rr++)
            ((float4*)out)[(base + rr) * 32 + lane] = *(const float4*)&OB[rr * OSTR + 4 * lane];
        __syncwarp();
    }
}

// ---------------- launch ----------------
extern "C" void kernel_launch(void* const* d_in, const int* in_sizes, int n_in,
                              void* d_out, int out_size) {
    const float* x1a     = (const float*)d_in[0];
    const float* x1b     = (const float*)d_in[1];
    const float* x2      = (const float*)d_in[2];
    const float* scalars = (const float*)d_in[3];
    const float* w0      = (const float*)d_in[4];
    const float* w1      = (const float*)d_in[5];
    const float* w2      = (const float*)d_in[6];
    const float* w3      = (const float*)d_in[7];
    const float* Wl0     = (const float*)d_in[8];
    const float* Wl1     = (const float*)d_in[9];
    const float* Wm1     = (const float*)d_in[10];
    const float* Wm2     = (const float*)d_in[11];
    const float* Wm3     = (const float*)d_in[12];
    const float* Wf0     = (const float*)d_in[13];
    const float* Wf1     = (const float*)d_in[14];
    int n = in_sizes[0] / 128;

    cudaFuncSetAttribute(tp_mma_kernel, cudaFuncAttributeMaxDynamicSharedMemorySize, SMEM_BYTES);

    prep_kernel<<<112, 256>>>(w0, w1, w2, w3, Wl0, Wl1, Wm1, Wm2, Wm3, Wf0, Wf1);
    tp_mma_kernel<<<148, 32 * NWARP, SMEM_BYTES>>>(x1a, x1b, (const float4*)x2, scalars,
                                                   (float*)d_out, n);
}

// round 10
// speedup vs baseline: 1.2855x; 1.2855x over previous
#include <cuda_runtime.h>
#include <math.h>

typedef unsigned int u32;

// weight buffer (floats): w3,WB,w0,w2 -> smem (critical TP loops); w1,WA,Wm1,Wm2,Wm3 -> GLOBAL (L2-hot)
#define FB_W3  0
#define FB_WB  2048
#define FB_W0  4096
#define FB_W2  6144
#define FB_SM  8192                // floats copied to smem
#define FB_W1  8192
#define FB_WA  10240
#define FB_WM1 12288
#define FB_WM2 16384
#define FB_WM3 20480
#define FB_TOT 28672

#define NWARP  12
#define TFL    1024                 // 16 x 64 tile (swizzled, no padding)
#define OSTR   132
#define ARENA  (4 * TFL)            // 4096 floats
#define SMEM_FLOATS (FB_SM + NWARP * ARENA)    // 8192 + 49152 = 57344
#define SMEM_BYTES  (SMEM_FLOATS * 4)          // 229376

__device__ float g_cst;
__device__ float g_wbuf[FB_TOT];

__device__ __forceinline__ u32 tf32(float f) {
    u32 u; asm("cvt.rna.tf32.f32 %0,%1;" : "=r"(u) : "f"(f)); return u;
}
__device__ __forceinline__ void split2(float x, u32& h, u32& l) {
    h = tf32(x);
    l = tf32(x - __uint_as_float(h));
}
__device__ __forceinline__ void mma_t(float* d, u32 a0, u32 a1, u32 a2, u32 a3,
                                      u32 b0, u32 b1) {
    asm("mma.sync.aligned.m16n8k8.row.col.f32.tf32.tf32.f32 "
        "{%0,%1,%2,%3},{%4,%5,%6,%7},{%8,%9},{%0,%1,%2,%3};"
        : "+f"(d[0]), "+f"(d[1]), "+f"(d[2]), "+f"(d[3])
        : "r"(a0), "r"(a1), "r"(a2), "r"(a3), "r"(b0), "r"(b1));
}

// acc[4*NT] += T[16x64 swizzled] @ W(smem)
template<int NT>
__device__ __forceinline__ void gemm16s(float* acc, const float* T, const float* W,
                                        int r4, int m4, int lane) {
    const int s4 = r4 << 2;
#pragma unroll
    for (int k8 = 0; k8 < 8; k8++) {
        int c0 = k8 * 8 + m4;
        u32 h0, l0, h1, l1, h2, l2, h3, l3;
        split2(T[r4 * 64 + (c0 ^ s4)],             h0, l0);
        split2(T[(r4 + 8) * 64 + (c0 ^ s4)],       h1, l1);
        split2(T[r4 * 64 + ((c0 + 4) ^ s4)],       h2, l2);
        split2(T[(r4 + 8) * 64 + ((c0 + 4) ^ s4)], h3, l3);
        const float* wp = W + k8 * NT * 64 + 2 * lane;
#pragma unroll
        for (int nt = 0; nt < NT; nt++) {
            uint2 b = *(const uint2*)(wp + nt * 64);
            mma_t(acc + 4 * nt, h0, h1, h2, h3, b.x, b.y);
            mma_t(acc + 4 * nt, l0, l1, l2, l3, b.x, b.y);
        }
    }
}

// same but W read from GLOBAL via __ldg (L2-hot)
template<int NT>
__device__ __forceinline__ void gemm16g(float* acc, const float* T, const float* W,
                                        int r4, int m4, int lane) {
    const int s4 = r4 << 2;
#pragma unroll
    for (int k8 = 0; k8 < 8; k8++) {
        int c0 = k8 * 8 + m4;
        u32 h0, l0, h1, l1, h2, l2, h3, l3;
        split2(T[r4 * 64 + (c0 ^ s4)],             h0, l0);
        split2(T[(r4 + 8) * 64 + (c0 ^ s4)],       h1, l1);
        split2(T[r4 * 64 + ((c0 + 4) ^ s4)],       h2, l2);
        split2(T[(r4 + 8) * 64 + ((c0 + 4) ^ s4)], h3, l3);
        const float* wp = W + k8 * NT * 64 + 2 * lane;
#pragma unroll
        for (int nt = 0; nt < NT; nt++) {
            uint2 b = __ldg((const uint2*)(wp + nt * 64));
            mma_t(acc + 4 * nt, h0, h1, h2, h3, b.x, b.y);
            mma_t(acc + 4 * nt, l0, l1, l2, l3, b.x, b.y);
        }
    }
}

// ---------------- prep ----------------
__global__ void prep_kernel(const float* __restrict__ w0, const float* __restrict__ w1,
                            const float* __restrict__ w2, const float* __restrict__ w3,
                            const float* __restrict__ Wl0, const float* __restrict__ Wl1,
                            const float* __restrict__ Wm1, const float* __restrict__ Wm2,
                            const float* __restrict__ Wm3,
                            const float* __restrict__ Wf0, const float* __restrict__ Wf1) {
    if (blockIdx.x == 0) {
        const int   N = 20000;
        const float h = 24.0f / 20000.0f;
        float local = 0.0f;
        for (int i = threadIdx.x; i <= N; i += blockDim.x) {
            float z   = -12.0f + h * (float)i;
            float s   = z / (1.0f + __expf(-z));
            float phi = __expf(-0.5f * z * z) * 0.3989422804014327f;
            float f   = s * s * phi;
            if (i == 0 || i == N) f *= 0.5f;
            local += f;
        }
        __shared__ float red[256];
        red[threadIdx.x] = local;
        __syncthreads();
        for (int s = 128; s > 0; s >>= 1) {
            if (threadIdx.x < s) red[threadIdx.x] += red[threadIdx.x + s];
            __syncthreads();
        }
        if (threadIdx.x == 0) g_cst = rsqrtf(red[0] * h);
    }

    int tid = blockIdx.x * blockDim.x + threadIdx.x;
    if (tid >= FB_TOT) return;
    const float INV_S3 = 0.57735026918962576f;
    const float WSCALE = 0.125f * 0.125f * 0.17677669529663687f;

    int mbase, N;
    if (tid < FB_WM1)          { mbase = (tid / 2048) * 2048; N = 32; }
    else if (tid < FB_WM2)     { mbase = FB_WM1; N = 64; }
    else if (tid < FB_WM3)     { mbase = FB_WM2; N = 64; }
    else                       { mbase = FB_WM3; N = 128; }
    int idx = tid - mbase;
    int g = idx >> 6, pos = idx & 63, l = pos >> 1, hh = pos & 1;
    int ntn = N >> 3, k8 = g / ntn, n8 = g % ntn;
    int row = k8 * 8 + (l & 3) + 4 * hh;   // K index
    int col = n8 * 8 + (l >> 2);           // N index

    float v;
    if (tid < FB_WM1) {
        int m = tid / 2048;   // 0:w3 1:WB 2:w0 3:w2 4:w1 5:WA
        if (m == 0)      v = w3[row * 32 + col];
        else if (m == 2) v = w0[row * 32 + col];
        else if (m == 3) v = w2[row * 32 + col];
        else if (m == 4) v = w1[row * 32 + col] * INV_S3;
        else {
            const float* L = (m == 1) ? Wl1 : Wl0;
            const float* F = (m == 1) ? Wf1 : Wf0;
            float acc = 0.0f;
            for (int w = 0; w < 32; w++) acc = fmaf(L[row * 32 + w], F[w * 32 + col], acc);
            v = acc * WSCALE;
        }
    }
    else if (tid < FB_WM2)     v = Wm1[row * 64 + col] * 0.125f;
    else if (tid < FB_WM3)     v = Wm2[row * 64 + col] * 0.125f;
    else                       v = Wm3[row * 128 + col] * 0.125f;
    g_wbuf[tid] = __uint_as_float(tf32(v));
}

// ---------------- main ----------------
__global__ __launch_bounds__(32 * NWARP, 1)
void tp_mma_kernel(const float* __restrict__ x1a, const float* __restrict__ x1b,
                   const float4* __restrict__ x2, const float* __restrict__ scalars,
                   float* __restrict__ out, int nrows) {
    extern __shared__ float smem[];
    {
        const float4* src = (const float4*)g_wbuf;
        float4* dst = (float4*)smem;
        for (int i = threadIdx.x; i < FB_SM / 4; i += 32 * NWARP) dst[i] = src[i];
    }
    __syncthreads();
    const float cst = g_cst;
    const float* w1g  = g_wbuf + FB_W1;
    const float* wag  = g_wbuf + FB_WA;
    const float* wm1g = g_wbuf + FB_WM1;
    const float* wm2g = g_wbuf + FB_WM2;
    const float* wm3g = g_wbuf + FB_WM3;

    const int lane = threadIdx.x & 31, wid = threadIdx.x >> 5;
    const int r4 = lane >> 2, m4 = lane & 3;
    const int s4 = r4 << 2;

    float* A0 = smem + FB_SM + wid * ARENA;
    float* A1 = A0 + TFL;
    float* A2 = A1 + TFL;
    float* A3 = A2 + TFL;

    const int gw = blockIdx.x * NWARP + wid, gwn = gridDim.x * NWARP;
    const int ntiles = nrows >> 4;

    for (int t = gw; t < ntiles; t += gwn) {
        const int base = t * 16;

        // ---- stage scalars (fp32, swizzled) ----
#pragma unroll
        for (int j = 0; j < 8; j++) {
            int row = r4 + 8 * (j & 1), f4 = m4 + 4 * (j >> 1);
            *(float4*)&A0[row * 64 + ((4 * f4) ^ s4)] =
                ((const float4*)scalars)[(base + row) * 16 + f4];
        }
        __syncwarp();

        // ---- MLP GEMM1 -> silu -> GEMM2 -> silu -> GEMM3 (weights via L2) ----
        float h[32];
#pragma unroll
        for (int i = 0; i < 32; i++) h[i] = 0.f;
        gemm16g<8>(h, A0, wm1g, r4, m4, lane);
        __syncwarp();
#pragma unroll
        for (int nt = 0; nt < 8; nt++) {
            float a = h[4 * nt],     b = h[4 * nt + 1];
            float c = h[4 * nt + 2], d = h[4 * nt + 3];
            float2 lo = {cst * a / (1.f + __expf(-a)), cst * b / (1.f + __expf(-b))};
            float2 hi = {cst * c / (1.f + __expf(-c)), cst * d / (1.f + __expf(-d))};
            int sc = (nt * 8 + 2 * m4) ^ s4;
            *(float2*)&A0[r4 * 64 + sc]       = lo;
            *(float2*)&A0[(r4 + 8) * 64 + sc] = hi;
        }
        __syncwarp();
#pragma unroll
        for (int i = 0; i < 32; i++) h[i] = 0.f;
        gemm16g<8>(h, A0, wm2g, r4, m4, lane);
        __syncwarp();
#pragma unroll
        for (int nt = 0; nt < 8; nt++) {
            float a = h[4 * nt],     b = h[4 * nt + 1];
            float c = h[4 * nt + 2], d = h[4 * nt + 3];
            float2 lo = {cst * a / (1.f + __expf(-a)), cst * b / (1.f + __expf(-b))};
            float2 hi = {cst * c / (1.f + __expf(-c)), cst * d / (1.f + __expf(-d))};
            int sc = (nt * 8 + 2 * m4) ^ s4;
            *(float2*)&A0[r4 * 64 + sc]       = lo;
            *(float2*)&A0[(r4 + 8) * 64 + sc] = hi;
        }
        __syncwarp();
        float wt[64];
#pragma unroll
        for (int i = 0; i < 64; i++) wt[i] = 0.f;
        gemm16g<16>(wt, A0, wm3g, r4, m4, lane);
        __syncwarp();

        // ---- stage x1 -> s0 (A0), s1k (A1..A3), fp32, swizzled ----
        for (int rr = 0; rr < 16; rr++) {
            int srr = (rr & 7) << 2;
            float4 va = ((const float4*)x1a)[(base + rr) * 32 + lane];
            float4 vb = ((const float4*)x1b)[(base + rr) * 32 + lane];
            if (lane < 8) {
                *(float4*)&A0[rr * 64 + ((4 * lane) ^ srr)]      = va;
                *(float4*)&A0[rr * 64 + 32 + ((4 * lane) ^ srr)] = vb;
            } else {
                int f = 4 * lane - 32;
                float av[4] = {va.x, va.y, va.z, va.w};
                float bv[4] = {vb.x, vb.y, vb.z, vb.w};
#pragma unroll
                for (int q = 0; q < 4; q++) {
                    int u = (f + q) / 3, k = (f + q) % 3;
                    float* Tk = (k == 0) ? A1 : ((k == 1) ? A2 : A3);
                    Tk[rr * 64 + (u ^ srr)]      = av[q];
                    Tk[rr * 64 + 32 + (u ^ srr)] = bv[q];
                }
            }
        }
        __syncwarp();

        // ---- y direct from global (L1-hot) ----
        float4 yA = __ldg(&x2[base + r4]);
        float4 yB = __ldg(&x2[base + r4 + 8]);
        const float y0A = yA.x, yA1 = yA.y, yA2 = yA.z, yA3 = yA.w;
        const float y0B = yB.x, yB1 = yB.y, yB2 = yB.z, yB3 = yB.w;

        // ---- G4/G5: R0 = s0@w0, Pp = s0@w2 (shared A frags; smem weights) ----
        float R0[16], Pp[16], R1[16];
#pragma unroll
        for (int i = 0; i < 16; i++) { R0[i] = 0.f; Pp[i] = 0.f; R1[i] = 0.f; }
#pragma unroll
        for (int k8 = 0; k8 < 8; k8++) {
            int c0 = k8 * 8 + m4;
            u32 h0, l0, h1, l1, h2, l2, h3, l3;
            split2(A0[r4 * 64 + (c0 ^ s4)],             h0, l0);
            split2(A0[(r4 + 8) * 64 + (c0 ^ s4)],       h1, l1);
            split2(A0[r4 * 64 + ((c0 + 4) ^ s4)],       h2, l2);
            split2(A0[(r4 + 8) * 64 + ((c0 + 4) ^ s4)], h3, l3);
            const float* w0p = smem + FB_W0 + k8 * 4 * 64 + 2 * lane;
            const float* w2p = smem + FB_W2 + k8 * 4 * 64 + 2 * lane;
#pragma unroll
            for (int nt = 0; nt < 4; nt++) {
                uint2 b0 = *(const uint2*)(w0p + nt * 64);
                mma_t(R0 + 4 * nt, h0, h1, h2, h3, b0.x, b0.y);
                mma_t(R0 + 4 * nt, l0, l1, l2, l3, b0.x, b0.y);
                uint2 b2 = *(const uint2*)(w2p + nt * 64);
                mma_t(Pp + 4 * nt, h0, h1, h2, h3, b2.x, b2.y);
                mma_t(Pp + 4 * nt, l0, l1, l2, l3, b2.x, b2.y);
            }
        }

        // ---- G6: R1 = t1@w1, t1 frags built on the fly (w1 via L2, overlapped by FMA build) ----
#pragma unroll
        for (int k8 = 0; k8 < 8; k8++) {
            int c0 = k8 * 8 + m4;
            int oa = r4 * 64 + (c0 ^ s4),       ob = (r4 + 8) * 64 + (c0 ^ s4);
            int oc = r4 * 64 + ((c0 + 4) ^ s4), od = (r4 + 8) * 64 + ((c0 + 4) ^ s4);
            float t0  = A1[oa] * yA1 + A2[oa] * yA2 + A3[oa] * yA3;
            float t1v = A1[ob] * yB1 + A2[ob] * yB2 + A3[ob] * yB3;
            float t2  = A1[oc] * yA1 + A2[oc] * yA2 + A3[oc] * yA3;
            float t3  = A1[od] * yB1 + A2[od] * yB2 + A3[od] * yB3;
            u32 h0, l0, h1, l1, h2, l2, h3, l3;
            split2(t0, h0, l0); split2(t1v, h1, l1);
            split2(t2, h2, l2); split2(t3, h3, l3);
            const float* w1p = w1g + k8 * 4 * 64 + 2 * lane;
#pragma unroll
            for (int nt = 0; nt < 4; nt++) {
                uint2 b = __ldg((const uint2*)(w1p + nt * 64));
                mma_t(R1 + 4 * nt, h0, h1, h2, h3, b.x, b.y);
                mma_t(R1 + 4 * nt, l0, l1, l2, l3, b.x, b.y);
            }
        }
        __syncwarp();   // s0 reads done -> overlay m0 on A0

        // ---- m0 build -> A0 ----
#pragma unroll
        for (int nt = 0; nt < 4; nt++) {
            int sc = (nt * 8 + 2 * m4) ^ s4;
            A0[r4 * 64 + sc]           = y0A * R0[4 * nt]     * wt[4 * nt];
            A0[r4 * 64 + sc + 1]       = y0A * R0[4 * nt + 1] * wt[4 * nt + 1];
            A0[(r4 + 8) * 64 + sc]     = y0B * R0[4 * nt + 2] * wt[4 * nt + 2];
            A0[(r4 + 8) * 64 + sc + 1] = y0B * R0[4 * nt + 3] * wt[4 * nt + 3];
            int wi = 4 * (nt + 4);
            int sc2 = (32 + nt * 8 + 2 * m4) ^ s4;
            A0[r4 * 64 + sc2]           = R1[4 * nt]     * wt[wi];
            A0[r4 * 64 + sc2 + 1]       = R1[4 * nt + 1] * wt[wi + 1];
            A0[(r4 + 8) * 64 + sc2]     = R1[4 * nt + 2] * wt[wi + 2];
            A0[(r4 + 8) * 64 + sc2 + 1] = R1[4 * nt + 3] * wt[wi + 3];
        }

        // ---- G7: Qk = s1k@w3 (smem; B shared across 3 chains) ----
        float Q[48];
#pragma unroll
        for (int i = 0; i < 48; i++) Q[i] = 0.f;
#pragma unroll
        for (int k8 = 0; k8 < 8; k8++) {
            int c0 = k8 * 8 + m4;
            int oa = r4 * 64 + (c0 ^ s4),       ob = (r4 + 8) * 64 + (c0 ^ s4);
            int oc = r4 * 64 + ((c0 + 4) ^ s4), od = (r4 + 8) * 64 + ((c0 + 4) ^ s4);
            u32 H[3][4], L[3][4];
#pragma unroll
            for (int k = 0; k < 3; k++) {
                const float* Tk = (k == 0) ? A1 : ((k == 1) ? A2 : A3);
                split2(Tk[oa], H[k][0], L[k][0]);
                split2(Tk[ob], H[k][1], L[k][1]);
                split2(Tk[oc], H[k][2], L[k][2]);
                split2(Tk[od], H[k][3], L[k][3]);
            }
            const float* w3p = smem + FB_W3 + k8 * 4 * 64 + 2 * lane;
#pragma unroll
            for (int nt = 0; nt < 4; nt++) {
                uint2 b = *(const uint2*)(w3p + nt * 64);
#pragma unroll
                for (int k = 0; k < 3; k++) {
                    mma_t(Q + 16 * k + 4 * nt, H[k][0], H[k][1], H[k][2], H[k][3], b.x, b.y);
                    mma_t(Q + 16 * k + 4 * nt, L[k][0], L[k][1], L[k][2], L[k][3], b.x, b.y);
                }
            }
        }
        __syncwarp();   // s1 reads done -> overlay m1k

        // ---- m1k build -> A1..A3 ----
#pragma unroll
        for (int k = 0; k < 3; k++) {
            float* Tk = (k == 0) ? A1 : ((k == 1) ? A2 : A3);
            float ykA = (k == 0) ? yA1 : ((k == 1) ? yA2 : yA3);
            float ykB = (k == 0) ? yB1 : ((k == 1) ? yB2 : yB3);
#pragma unroll
            for (int nt = 0; nt < 4; nt++) {
                int wi = 4 * (nt + 8), wj = 4 * (nt + 12);
                int sc  = (nt * 8 + 2 * m4) ^ s4;
                int sc2 = (32 + nt * 8 + 2 * m4) ^ s4;
                Tk[r4 * 64 + sc]           = ykA * Pp[4 * nt]     * wt[wi];
                Tk[r4 * 64 + sc + 1]       = ykA * Pp[4 * nt + 1] * wt[wi + 1];
                Tk[(r4 + 8) * 64 + sc]     = ykB * Pp[4 * nt + 2] * wt[wi + 2];
                Tk[(r4 + 8) * 64 + sc + 1] = ykB * Pp[4 * nt + 3] * wt[wi + 3];
                Tk[r4 * 64 + sc2]           = y0A * Q[16 * k + 4 * nt]     * wt[wj];
                Tk[r4 * 64 + sc2 + 1]       = y0A * Q[16 * k + 4 * nt + 1] * wt[wj + 1];
                Tk[(r4 + 8) * 64 + sc2]     = y0B * Q[16 * k + 4 * nt + 2] * wt[wj + 2];
                Tk[(r4 + 8) * 64 + sc2 + 1] = y0B * Q[16 * k + 4 * nt + 3] * wt[wj + 3];
            }
        }
        __syncwarp();

        // ---- G8: O0 = m0@WA (L2, batched) ; G9: Ok = m1k@WB (smem, B shared) ----
        float O0[16];
#pragma unroll
        for (int i = 0; i < 16; i++) O0[i] = 0.f;
        gemm16g<4>(O0, A0, wag, r4, m4, lane);

        float O[48];
#pragma unroll
        for (int i = 0; i < 48; i++) O[i] = 0.f;
#pragma unroll
        for (int k8 = 0; k8 < 8; k8++) {
            int c0 = k8 * 8 + m4;
            int oa = r4 * 64 + (c0 ^ s4),       ob = (r4 + 8) * 64 + (c0 ^ s4);
            int oc = r4 * 64 + ((c0 + 4) ^ s4), od = (r4 + 8) * 64 + ((c0 + 4) ^ s4);
            u32 H[3][4], L[3][4];
#pragma unroll
            for (int k = 0; k < 3; k++) {
                const float* Tk = (k == 0) ? A1 : ((k == 1) ? A2 : A3);
                split2(Tk[oa], H[k][0], L[k][0]);
                split2(Tk[ob], H[k][1], L[k][1]);
                split2(Tk[oc], H[k][2], L[k][2]);
                split2(Tk[od], H[k][3], L[k][3]);
            }
            const float* wbp = smem + FB_WB + k8 * 4 * 64 + 2 * lane;
#pragma unroll
            for (int nt = 0; nt < 4; nt++) {
                uint2 b = *(const uint2*)(wbp + nt * 64);
#pragma unroll
                for (int k = 0; k < 3; k++) {
                    mma_t(O + 16 * k + 4 * nt, H[k][0], H[k][1], H[k][2], H[k][3], b.x, b.y);
                    mma_t(O + 16 * k + 4 * nt, L[k][0], L[k][1], L[k][2], L[k][3], b.x, b.y);
                }
            }
        }
        __syncwarp();   // m reads done -> overlay out staging on arena

        // ---- stage outputs (OB = A0 base, stride OSTR, linear overlay) ----
        float* OB = A0;
#pragma unroll
        for (int nt = 0; nt < 4; nt++) {
            int u = nt * 8 + 2 * m4;
            OB[r4 * OSTR + u]           = O0[4 * nt];
            OB[r4 * OSTR + u + 1]       = O0[4 * nt + 1];
            OB[(r4 + 8) * OSTR + u]     = O0[4 * nt + 2];
            OB[(r4 + 8) * OSTR + u + 1] = O0[4 * nt + 3];
#pragma unroll
            for (int k = 0; k < 3; k++) {
                int c = 32 + 3 * u + k;
                OB[r4 * OSTR + c]           = O[16 * k + 4 * nt];
                OB[r4 * OSTR + c + 3]       = O[16 * k + 4 * nt + 1];
                OB[(r4 + 8) * OSTR + c]     = O[16 * k + 4 * nt + 2];
                OB[(r4 + 8) * OSTR + c + 3] = O[16 * k + 4 * nt + 3];
            }
        }
        __syncwarp();
#pragma unroll
        for (int rr = 0; rr < 16; rr++)
            ((float4*)out)[(base + rr) * 32 + lane] = *(const float4*)&OB[rr * OSTR + 4 * lane];
        __syncwarp();
    }
}

// ---------------- launch ----------------
extern "C" void kernel_launch(void* const* d_in, const int* in_sizes, int n_in,
                              void* d_out, int out_size) {
    const float* x1a     = (const float*)d_in[0];
    const float* x1b     = (const float*)d_in[1];
    const float* x2      = (const float*)d_in[2];
    const float* scalars = (const float*)d_in[3];
    const float* w0      = (const float*)d_in[4];
    const float* w1      = (const float*)d_in[5];
    const float* w2      = (const float*)d_in[6];
    const float* w3      = (const float*)d_in[7];
    const float* Wl0     = (const float*)d_in[8];
    const float* Wl1     = (const float*)d_in[9];
    const float* Wm1     = (const float*)d_in[10];
    const float* Wm2     = (const float*)d_in[11];
    const float* Wm3     = (const float*)d_in[12];
    const float* Wf0     = (const float*)d_in[13];
    const float* Wf1     = (const float*)d_in[14];
    int n = in_sizes[0] / 128;

    cudaFuncSetAttribute(tp_mma_kernel, cudaFuncAttributeMaxDynamicSharedMemorySize, SMEM_BYTES);

    prep_kernel<<<112, 256>>>(w0, w1, w2, w3, Wl0, Wl1, Wm1, Wm2, Wm3, Wf0, Wf1);
    tp_mma_kernel<<<148, 32 * NWARP, SMEM_BYTES>>>(x1a, x1b, (const float4*)x2, scalars,
                                                   (float*)d_out, n);
}

// round 11
// speedup vs baseline: 1.3130x; 1.0213x over previous
#include <cuda_runtime.h>
#include <math.h>

typedef unsigned int u32;

// weight buffer (floats): six small matrices -> smem; Wm1/Wm2/Wm3 stay in GLOBAL (L2-hot)
#define FB_W0  0
#define FB_W1  2048
#define FB_W2  4096
#define FB_W3  6144
#define FB_WA  8192
#define FB_WB  10240
#define FB_SM  12288               // floats copied to smem
#define FB_WM1 12288
#define FB_WM2 16384
#define FB_WM3 20480
#define FB_TOT 28672

#define NWARP  10
#define TSTR   68
#define TFL    (16 * TSTR)          // 1088
#define OSTR   132
#define ARENA  (4 * TFL)            // 4352 floats; Yt lives in A3 column padding
#define SMEM_FLOATS (FB_SM + NWARP * ARENA)    // 12288 + 43520 = 55808
#define SMEM_BYTES  (SMEM_FLOATS * 4)          // 223232

__device__ float g_cst;
__device__ float g_wbuf[FB_TOT];

__device__ __forceinline__ u32 tf32(float f) {
    u32 u; asm("cvt.rna.tf32.f32 %0,%1;" : "=r"(u) : "f"(f)); return u;
}
__device__ __forceinline__ void mma_t(float* d, u32 a0, u32 a1, u32 a2, u32 a3,
                                      u32 b0, u32 b1) {
    asm("mma.sync.aligned.m16n8k8.row.col.f32.tf32.tf32.f32 "
        "{%0,%1,%2,%3},{%4,%5,%6,%7},{%8,%9},{%0,%1,%2,%3};"
        : "+f"(d[0]), "+f"(d[1]), "+f"(d[2]), "+f"(d[3])
        : "r"(a0), "r"(a1), "r"(a2), "r"(a3), "r"(b0), "r"(b1));
}

// acc[4*NT] += T[16x64] @ W(smem) ; single-tf32 A and W
template<int NT>
__device__ __forceinline__ void gemm16s(float* acc, const float* T, const float* W,
                                        int r4, int m4, int lane) {
#pragma unroll
    for (int k8 = 0; k8 < 8; k8++) {
        const float* ap = T + r4 * TSTR + k8 * 8 + m4;
        u32 a0 = tf32(ap[0]);
        u32 a1 = tf32(ap[8 * TSTR]);
        u32 a2 = tf32(ap[4]);
        u32 a3 = tf32(ap[8 * TSTR + 4]);
        const float* wp = W + k8 * NT * 64 + 2 * lane;
#pragma unroll
        for (int nt = 0; nt < NT; nt++) {
            uint2 b = *(const uint2*)(wp + nt * 64);
            mma_t(acc + 4 * nt, a0, a1, a2, a3, b.x, b.y);
        }
    }
}

// same but W read from GLOBAL via __ldg (Wm1/Wm2/Wm3, L2-hot)
template<int NT>
__device__ __forceinline__ void gemm16g(float* acc, const float* T, const float* W,
                                        int r4, int m4, int lane) {
#pragma unroll
    for (int k8 = 0; k8 < 8; k8++) {
        const float* ap = T + r4 * TSTR + k8 * 8 + m4;
        u32 a0 = tf32(ap[0]);
        u32 a1 = tf32(ap[8 * TSTR]);
        u32 a2 = tf32(ap[4]);
        u32 a3 = tf32(ap[8 * TSTR + 4]);
        const float* wp = W + k8 * NT * 64 + 2 * lane;
#pragma unroll
        for (int nt = 0; nt < NT; nt++) {
            uint2 b = __ldg((const uint2*)(wp + nt * 64));
            mma_t(acc + 4 * nt, a0, a1, a2, a3, b.x, b.y);
        }
    }
}

// ---------------- prep ----------------
__global__ void prep_kernel(const float* __restrict__ w0, const float* __restrict__ w1,
                            const float* __restrict__ w2, const float* __restrict__ w3,
                            const float* __restrict__ Wl0, const float* __restrict__ Wl1,
                            const float* __restrict__ Wm1, const float* __restrict__ Wm2,
                            const float* __restrict__ Wm3,
                            const float* __restrict__ Wf0, const float* __restrict__ Wf1) {
    if (blockIdx.x == 0) {
        const int   N = 20000;
        const float h = 24.0f / 20000.0f;
        float local = 0.0f;
        for (int i = threadIdx.x; i <= N; i += blockDim.x) {
            float z   = -12.0f + h * (float)i;
            float s   = z / (1.0f + __expf(-z));
            float phi = __expf(-0.5f * z * z) * 0.3989422804014327f;
            float f   = s * s * phi;
            if (i == 0 || i == N) f *= 0.5f;
            local += f;
        }
        __shared__ float red[256];
        red[threadIdx.x] = local;
        __syncthreads();
        for (int s = 128; s > 0; s >>= 1) {
            if (threadIdx.x < s) red[threadIdx.x] += red[threadIdx.x + s];
            __syncthreads();
        }
        if (threadIdx.x == 0) g_cst = rsqrtf(red[0] * h);
    }

    int tid = blockIdx.x * blockDim.x + threadIdx.x;
    if (tid >= FB_TOT) return;
    const float INV_S3 = 0.57735026918962576f;
    const float WSCALE = 0.125f * 0.125f * 0.17677669529663687f;

    int mbase, N;
    if (tid < FB_SM)           { mbase = (tid / 2048) * 2048; N = 32; }
    else if (tid < FB_WM2)     { mbase = FB_WM1; N = 64; }
    else if (tid < FB_WM3)     { mbase = FB_WM2; N = 64; }
    else                       { mbase = FB_WM3; N = 128; }
    int idx = tid - mbase;
    int g = idx >> 6, pos = idx & 63, l = pos >> 1, hh = pos & 1;
    int ntn = N >> 3, k8 = g / ntn, n8 = g % ntn;
    int row = k8 * 8 + (l & 3) + 4 * hh;   // K index
    int col = n8 * 8 + (l >> 2);           // N index

    float v;
    if (tid < 2048)            v = w0[row * 32 + col];
    else if (tid < 4096)       v = w1[row * 32 + col] * INV_S3;
    else if (tid < 6144)       v = w2[row * 32 + col];
    else if (tid < 8192)       v = w3[row * 32 + col];
    else if (tid < FB_SM) {
        const float* L = (tid < 10240) ? Wl0 : Wl1;
        const float* F = (tid < 10240) ? Wf0 : Wf1;
        float acc = 0.0f;
        for (int w = 0; w < 32; w++) acc = fmaf(L[row * 32 + w], F[w * 32 + col], acc);
        v = acc * WSCALE;
    }
    else if (tid < FB_WM2)     v = Wm1[row * 64 + col] * 0.125f;
    else if (tid < FB_WM3)     v = Wm2[row * 64 + col] * 0.125f;
    else                       v = Wm3[row * 128 + col] * 0.125f;
    g_wbuf[tid] = __uint_as_float(tf32(v));
}

// ---------------- main ----------------
__global__ __launch_bounds__(32 * NWARP, 1)
void tp_mma_kernel(const float* __restrict__ x1a, const float* __restrict__ x1b,
                   const float4* __restrict__ x2, const float* __restrict__ scalars,
                   float* __restrict__ out, int nrows) {
    extern __shared__ float smem[];
    {
        const float4* src = (const float4*)g_wbuf;
        float4* dst = (float4*)smem;
        for (int i = threadIdx.x; i < FB_SM / 4; i += 32 * NWARP) dst[i] = src[i];
    }
    __syncthreads();
    const float cst = g_cst;
    const float* wm1g = g_wbuf + FB_WM1;
    const float* wm2g = g_wbuf + FB_WM2;
    const float* wm3g = g_wbuf + FB_WM3;

    const int lane = threadIdx.x & 31, wid = threadIdx.x >> 5;
    const int r4 = lane >> 2, m4 = lane & 3;

    float* A0 = smem + FB_SM + wid * ARENA;
    float* A1 = A0 + TFL;
    float* A2 = A1 + TFL;
    float* A3 = A2 + TFL;
    // Yt lives in A3 column padding: row rr -> A3[rr*TSTR + 64 .. 68)

    const int gw = blockIdx.x * NWARP + wid, gwn = gridDim.x * NWARP;
    const int ntiles = nrows >> 4;

    for (int t = gw; t < ntiles; t += gwn) {
        const int base = t * 16;

        // ---- stage scalars (fp32) + y (into A3 padding) ----
#pragma unroll
        for (int j = 0; j < 8; j++) {
            int row = r4 + 8 * (j & 1), f4 = m4 + 4 * (j >> 1);
            *(float4*)&A0[row * TSTR + 4 * f4] =
                ((const float4*)scalars)[(base + row) * 16 + f4];
        }
        if (lane < 16) *(float4*)&A3[lane * TSTR + 64] = x2[base + lane];
        __syncwarp();

        // ---- MLP GEMM1 -> silu -> GEMM2 -> silu -> GEMM3 (weights via L2) ----
        float h[32];
#pragma unroll
        for (int i = 0; i < 32; i++) h[i] = 0.f;
        gemm16g<8>(h, A0, wm1g, r4, m4, lane);
        __syncwarp();
#pragma unroll
        for (int nt = 0; nt < 8; nt++) {
            float a = h[4 * nt],     b = h[4 * nt + 1];
            float c = h[4 * nt + 2], d = h[4 * nt + 3];
            float2 lo = {cst * a / (1.f + __expf(-a)), cst * b / (1.f + __expf(-b))};
            float2 hi = {cst * c / (1.f + __expf(-c)), cst * d / (1.f + __expf(-d))};
            *(float2*)&A0[r4 * TSTR + nt * 8 + 2 * m4]       = lo;
            *(float2*)&A0[(r4 + 8) * TSTR + nt * 8 + 2 * m4] = hi;
        }
        __syncwarp();
#pragma unroll
        for (int i = 0; i < 32; i++) h[i] = 0.f;
        gemm16g<8>(h, A0, wm2g, r4, m4, lane);
        __syncwarp();
#pragma unroll
        for (int nt = 0; nt < 8; nt++) {
            float a = h[4 * nt],     b = h[4 * nt + 1];
            float c = h[4 * nt + 2], d = h[4 * nt + 3];
            float2 lo = {cst * a / (1.f + __expf(-a)), cst * b / (1.f + __expf(-b))};
            float2 hi = {cst * c / (1.f + __expf(-c)), cst * d / (1.f + __expf(-d))};
            *(float2*)&A0[r4 * TSTR + nt * 8 + 2 * m4]       = lo;
            *(float2*)&A0[(r4 + 8) * TSTR + nt * 8 + 2 * m4] = hi;
        }
        __syncwarp();
        float wt[64];
#pragma unroll
        for (int i = 0; i < 64; i++) wt[i] = 0.f;
        gemm16g<16>(wt, A0, wm3g, r4, m4, lane);
        __syncwarp();

        // ---- stage x1 -> s0 (A0), s1k (A1..A3), fp32 ----
        for (int rr = 0; rr < 16; rr++) {
            float4 va = ((const float4*)x1a)[(base + rr) * 32 + lane];
            float4 vb = ((const float4*)x1b)[(base + rr) * 32 + lane];
            if (lane < 8) {
                *(float4*)&A0[rr * TSTR + 4 * lane]      = va;
                *(float4*)&A0[rr * TSTR + 32 + 4 * lane] = vb;
            } else {
                int f = 4 * lane - 32;
                float av[4] = {va.x, va.y, va.z, va.w};
                float bv[4] = {vb.x, vb.y, vb.z, vb.w};
#pragma unroll
                for (int q = 0; q < 4; q++) {
                    int u = (f + q) / 3, k = (f + q) % 3;
                    float* Tk = (k == 0) ? A1 : ((k == 1) ? A2 : A3);
                    Tk[rr * TSTR + u]      = av[q];
                    Tk[rr * TSTR + 32 + u] = bv[q];
                }
            }
        }
        __syncwarp();

        const float y0A = A3[r4 * TSTR + 64],       y0B = A3[(r4 + 8) * TSTR + 64];
        const float yA1 = A3[r4 * TSTR + 65],       yB1 = A3[(r4 + 8) * TSTR + 65];
        const float yA2 = A3[r4 * TSTR + 66],       yB2 = A3[(r4 + 8) * TSTR + 66];
        const float yA3 = A3[r4 * TSTR + 67],       yB3 = A3[(r4 + 8) * TSTR + 67];

        // ---- G4/G5: R0 = s0@w0, Pp = s0@w2 (shared A frags) ----
        float R0[16], Pp[16], R1[16];
#pragma unroll
        for (int i = 0; i < 16; i++) { R0[i] = 0.f; Pp[i] = 0.f; R1[i] = 0.f; }
#pragma unroll
        for (int k8 = 0; k8 < 8; k8++) {
            const float* ap = A0 + r4 * TSTR + k8 * 8 + m4;
            u32 a0 = tf32(ap[0]);
            u32 a1 = tf32(ap[8 * TSTR]);
            u32 a2 = tf32(ap[4]);
            u32 a3 = tf32(ap[8 * TSTR + 4]);
            const float* w0p = smem + FB_W0 + k8 * 4 * 64 + 2 * lane;
            const float* w2p = smem + FB_W2 + k8 * 4 * 64 + 2 * lane;
#pragma unroll
            for (int nt = 0; nt < 4; nt++) {
                uint2 b0 = *(const uint2*)(w0p + nt * 64);
                mma_t(R0 + 4 * nt, a0, a1, a2, a3, b0.x, b0.y);
                uint2 b2 = *(const uint2*)(w2p + nt * 64);
                mma_t(Pp + 4 * nt, a0, a1, a2, a3, b2.x, b2.y);
            }
        }

        // ---- G6: R1 = t1@w1, t1 frags built on the fly ----
#pragma unroll
        for (int k8 = 0; k8 < 8; k8++) {
            int o = r4 * TSTR + k8 * 8 + m4;
            float t0  = A1[o] * yA1 + A2[o] * yA2 + A3[o] * yA3;
            float t2  = A1[o + 4] * yA1 + A2[o + 4] * yA2 + A3[o + 4] * yA3;
            float t1v = A1[o + 8 * TSTR] * yB1 + A2[o + 8 * TSTR] * yB2 + A3[o + 8 * TSTR] * yB3;
            float t3  = A1[o + 8 * TSTR + 4] * yB1 + A2[o + 8 * TSTR + 4] * yB2 + A3[o + 8 * TSTR + 4] * yB3;
            u32 a0 = tf32(t0), a1 = tf32(t1v), a2 = tf32(t2), a3 = tf32(t3);
            const float* w1p = smem + FB_W1 + k8 * 4 * 64 + 2 * lane;
#pragma unroll
            for (int nt = 0; nt < 4; nt++) {
                uint2 b = *(const uint2*)(w1p + nt * 64);
                mma_t(R1 + 4 * nt, a0, a1, a2, a3, b.x, b.y);
            }
        }
        __syncwarp();   // s0 reads done -> overlay m0 on A0

        // ---- m0 build -> A0 ----
#pragma unroll
        for (int nt = 0; nt < 4; nt++) {
            A0[r4 * TSTR + nt * 8 + 2 * m4]           = y0A * R0[4 * nt]     * wt[4 * nt];
            A0[r4 * TSTR + nt * 8 + 2 * m4 + 1]       = y0A * R0[4 * nt + 1] * wt[4 * nt + 1];
            A0[(r4 + 8) * TSTR + nt * 8 + 2 * m4]     = y0B * R0[4 * nt + 2] * wt[4 * nt + 2];
            A0[(r4 + 8) * TSTR + nt * 8 + 2 * m4 + 1] = y0B * R0[4 * nt + 3] * wt[4 * nt + 3];
            int wi = 4 * (nt + 4);
            A0[r4 * TSTR + 32 + nt * 8 + 2 * m4]           = R1[4 * nt]     * wt[wi];
            A0[r4 * TSTR + 32 + nt * 8 + 2 * m4 + 1]       = R1[4 * nt + 1] * wt[wi + 1];
            A0[(r4 + 8) * TSTR + 32 + nt * 8 + 2 * m4]     = R1[4 * nt + 2] * wt[wi + 2];
            A0[(r4 + 8) * TSTR + 32 + nt * 8 + 2 * m4 + 1] = R1[4 * nt + 3] * wt[wi + 3];
        }

        // ---- G7: Qk = s1k@w3 (B shared across k) ----
        float Q[48];
#pragma unroll
        for (int i = 0; i < 48; i++) Q[i] = 0.f;
#pragma unroll
        for (int k8 = 0; k8 < 8; k8++) {
            u32 A[3][4];
#pragma unroll
            for (int k = 0; k < 3; k++) {
                const float* Tk = (k == 0) ? A1 : ((k == 1) ? A2 : A3);
                int o = r4 * TSTR + k8 * 8 + m4;
                A[k][0] = tf32(Tk[o]);
                A[k][1] = tf32(Tk[o + 8 * TSTR]);
                A[k][2] = tf32(Tk[o + 4]);
                A[k][3] = tf32(Tk[o + 8 * TSTR + 4]);
            }
            const float* w3p = smem + FB_W3 + k8 * 4 * 64 + 2 * lane;
#pragma unroll
            for (int nt = 0; nt < 4; nt++) {
                uint2 b = *(const uint2*)(w3p + nt * 64);
#pragma unroll
                for (int k = 0; k < 3; k++)
                    mma_t(Q + 16 * k + 4 * nt, A[k][0], A[k][1], A[k][2], A[k][3], b.x, b.y);
            }
        }
        __syncwarp();   // s1 reads done -> overlay m1k

        // ---- m1k build -> A1..A3 ----
#pragma unroll
        for (int k = 0; k < 3; k++) {
            float* Tk = (k == 0) ? A1 : ((k == 1) ? A2 : A3);
            float ykA = (k == 0) ? yA1 : ((k == 1) ? yA2 : yA3);
            float ykB = (k == 0) ? yB1 : ((k == 1) ? yB2 : yB3);
#pragma unroll
            for (int nt = 0; nt < 4; nt++) {
                int wi = 4 * (nt + 8), wj = 4 * (nt + 12);
                Tk[r4 * TSTR + nt * 8 + 2 * m4]           = ykA * Pp[4 * nt]     * wt[wi];
                Tk[r4 * TSTR + nt * 8 + 2 * m4 + 1]       = ykA * Pp[4 * nt + 1] * wt[wi + 1];
                Tk[(r4 + 8) * TSTR + nt * 8 + 2 * m4]     = ykB * Pp[4 * nt + 2] * wt[wi + 2];
                Tk[(r4 + 8) * TSTR + nt * 8 + 2 * m4 + 1] = ykB * Pp[4 * nt + 3] * wt[wi + 3];
                Tk[r4 * TSTR + 32 + nt * 8 + 2 * m4]           = y0A * Q[16 * k + 4 * nt]     * wt[wj];
                Tk[r4 * TSTR + 32 + nt * 8 + 2 * m4 + 1]       = y0A * Q[16 * k + 4 * nt + 1] * wt[wj + 1];
                Tk[(r4 + 8) * TSTR + 32 + nt * 8 + 2 * m4]     = y0B * Q[16 * k + 4 * nt + 2] * wt[wj + 2];
                Tk[(r4 + 8) * TSTR + 32 + nt * 8 + 2 * m4 + 1] = y0B * Q[16 * k + 4 * nt + 3] * wt[wj + 3];
            }
        }
        __syncwarp();

        // ---- G8: O0 = m0@WA ; G9: Ok = m1k@WB (B shared) ----
        float O0[16];
#pragma unroll
        for (int i = 0; i < 16; i++) O0[i] = 0.f;
        gemm16s<4>(O0, A0, smem + FB_WA, r4, m4, lane);

        float O[48];
#pragma unroll
        for (int i = 0; i < 48; i++) O[i] = 0.f;
#pragma unroll
        for (int k8 = 0; k8 < 8; k8++) {
            u32 A[3][4];
#pragma unroll
            for (int k = 0; k < 3; k++) {
                const float* Tk = (k == 0) ? A1 : ((k == 1) ? A2 : A3);
                int o = r4 * TSTR + k8 * 8 + m4;
                A[k][0] = tf32(Tk[o]);
                A[k][1] = tf32(Tk[o + 8 * TSTR]);
                A[k][2] = tf32(Tk[o + 4]);
                A[k][3] = tf32(Tk[o + 8 * TSTR + 4]);
            }
            const float* wbp = smem + FB_WB + k8 * 4 * 64 + 2 * lane;
#pragma unroll
            for (int nt = 0; nt < 4; nt++) {
                uint2 b = *(const uint2*)(wbp + nt * 64);
#pragma unroll
                for (int k = 0; k < 3; k++)
                    mma_t(O + 16 * k + 4 * nt, A[k][0], A[k][1], A[k][2], A[k][3], b.x, b.y);
            }
        }
        __syncwarp();   // m reads done -> overlay out staging on A0/A1

        // ---- stage outputs (OB = A0, stride OSTR) ----
        float* OB = A0;
#pragma unroll
        for (int nt = 0; nt < 4; nt++) {
            int u = nt * 8 + 2 * m4;
            OB[r4 * OSTR + u]           = O0[4 * nt];
            OB[r4 * OSTR + u + 1]       = O0[4 * nt + 1];
            OB[(r4 + 8) * OSTR + u]     = O0[4 * nt + 2];
            OB[(r4 + 8) * OSTR + u + 1] = O0[4 * nt + 3];
#pragma unroll
            for (int k = 0; k < 3; k++) {
                int c = 32 + 3 * u + k;
                OB[r4 * OSTR + c]           = O[16 * k + 4 * nt];
                OB[r4 * OSTR + c + 3]       = O[16 * k + 4 * nt + 1];
                OB[(r4 + 8) * OSTR + c]     = O[16 * k + 4 * nt + 2];
                OB[(r4 + 8) * OSTR + c + 3] = O[16 * k + 4 * nt + 3];
            }
        }
        __syncwarp();
#pragma unroll
        for (int rr = 0; rr < 16; rr++)
            ((float4*)out)[(base + rr) * 32 + lane] = *(const float4*)&OB[rr * OSTR + 4 * lane];
        __syncwarp();
    }
}

// ---------------- launch ----------------
extern "C" void kernel_launch(void* const* d_in, const int* in_sizes, int n_in,
                              void* d_out, int out_size) {
    const float* x1a     = (const float*)d_in[0];
    const float* x1b     = (const float*)d_in[1];
    const float* x2      = (const float*)d_in[2];
    const float* scalars = (const float*)d_in[3];
    const float* w0      = (const float*)d_in[4];
    const float* w1      = (const float*)d_in[5];
    const float* w2      = (const float*)d_in[6];
    const float* w3      = (const float*)d_in[7];
    const float* Wl0     = (const float*)d_in[8];
    const float* Wl1     = (const float*)d_in[9];
    const float* Wm1     = (const float*)d_in[10];
    const float* Wm2     = (const float*)d_in[11];
    const float* Wm3     = (const float*)d_in[12];
    const float* Wf0     = (const float*)d_in[13];
    const float* Wf1     = (const float*)d_in[14];
    int n = in_sizes[0] / 128;

    cudaFuncSetAttribute(tp_mma_kernel, cudaFuncAttributeMaxDynamicSharedMemorySize, SMEM_BYTES);

    prep_kernel<<<112, 256>>>(w0, w1, w2, w3, Wl0, Wl1, Wm1, Wm2, Wm3, Wf0, Wf1);
    tp_mma_kernel<<<148, 32 * NWARP, SMEM_BYTES>>>(x1a, x1b, (const float4*)x2, scalars,
                                                   (float*)d_out, n);
}

// round 12
// speedup vs baseline: 2.2120x; 1.6847x over previous
#include <cuda_runtime.h>
#include <math.h>

typedef unsigned int u32;

// weight buffer (floats): six small matrices -> smem; Wm1/Wm2/Wm3 stay in GLOBAL (L2-hot)
#define FB_W0  0
#define FB_W1  2048
#define FB_W2  4096
#define FB_W3  6144
#define FB_WA  8192
#define FB_WB  10240
#define FB_SM  12288               // floats copied to smem
#define FB_WM1 12288
#define FB_WM2 16384
#define FB_WM3 20480
#define FB_TOT 28672

#define NWARP  10
#define TSTR   68
#define TFL    (16 * TSTR)          // 1088
#define OSTR   132
#define ARENA  (4 * TFL)            // 4352 floats
#define SMEM_FLOATS (FB_SM + NWARP * ARENA)    // 12288 + 43520 = 55808
#define SMEM_BYTES  (SMEM_FLOATS * 4)          // 223232

__device__ float g_cst;
__device__ float g_wbuf[FB_TOT];

__device__ __forceinline__ u32 tf32(float f) {
    u32 u; asm("cvt.rna.tf32.f32 %0,%1;" : "=r"(u) : "f"(f)); return u;
}
__device__ __forceinline__ void mma_t(float* d, u32 a0, u32 a1, u32 a2, u32 a3,
                                      u32 b0, u32 b1) {
    asm("mma.sync.aligned.m16n8k8.row.col.f32.tf32.tf32.f32 "
        "{%0,%1,%2,%3},{%4,%5,%6,%7},{%8,%9},{%0,%1,%2,%3};"
        : "+f"(d[0]), "+f"(d[1]), "+f"(d[2]), "+f"(d[3])
        : "r"(a0), "r"(a1), "r"(a2), "r"(a3), "r"(b0), "r"(b1));
}

// acc[4*NT] += T[16x64] @ W(smem) ; single-tf32 A and W
template<int NT>
__device__ __forceinline__ void gemm16s(float* acc, const float* T, const float* W,
                                        int r4, int m4, int lane) {
#pragma unroll
    for (int k8 = 0; k8 < 8; k8++) {
        const float* ap = T + r4 * TSTR + k8 * 8 + m4;
        u32 a0 = tf32(ap[0]);
        u32 a1 = tf32(ap[8 * TSTR]);
        u32 a2 = tf32(ap[4]);
        u32 a3 = tf32(ap[8 * TSTR + 4]);
        const float* wp = W + k8 * NT * 64 + 2 * lane;
#pragma unroll
        for (int nt = 0; nt < NT; nt++) {
            uint2 b = *(const uint2*)(wp + nt * 64);
            mma_t(acc + 4 * nt, a0, a1, a2, a3, b.x, b.y);
        }
    }
}

// same but W read from GLOBAL via __ldg (Wm1/Wm2/Wm3, L2-hot)
template<int NT>
__device__ __forceinline__ void gemm16g(float* acc, const float* T, const float* W,
                                        int r4, int m4, int lane) {
#pragma unroll
    for (int k8 = 0; k8 < 8; k8++) {
        const float* ap = T + r4 * TSTR + k8 * 8 + m4;
        u32 a0 = tf32(ap[0]);
        u32 a1 = tf32(ap[8 * TSTR]);
        u32 a2 = tf32(ap[4]);
        u32 a3 = tf32(ap[8 * TSTR + 4]);
        const float* wp = W + k8 * NT * 64 + 2 * lane;
#pragma unroll
        for (int nt = 0; nt < NT; nt++) {
            uint2 b = __ldg((const uint2*)(wp + nt * 64));
            mma_t(acc + 4 * nt, a0, a1, a2, a3, b.x, b.y);
        }
    }
}

// ---------------- prep ----------------
__global__ void prep_kernel(const float* __restrict__ w0, const float* __restrict__ w1,
                            const float* __restrict__ w2, const float* __restrict__ w3,
                            const float* __restrict__ Wl0, const float* __restrict__ Wl1,
                            const float* __restrict__ Wm1, const float* __restrict__ Wm2,
                            const float* __restrict__ Wm3,
                            const float* __restrict__ Wf0, const float* __restrict__ Wf1) {
    if (blockIdx.x == 0) {
        const int   N = 20000;
        const float h = 24.0f / 20000.0f;
        float local = 0.0f;
        for (int i = threadIdx.x; i <= N; i += blockDim.x) {
            float z   = -12.0f + h * (float)i;
            float s   = z / (1.0f + __expf(-z));
            float phi = __expf(-0.5f * z * z) * 0.3989422804014327f;
            float f   = s * s * phi;
            if (i == 0 || i == N) f *= 0.5f;
            local += f;
        }
        __shared__ float red[256];
        red[threadIdx.x] = local;
        __syncthreads();
        for (int s = 128; s > 0; s >>= 1) {
            if (threadIdx.x < s) red[threadIdx.x] += red[threadIdx.x + s];
            __syncthreads();
        }
        if (threadIdx.x == 0) g_cst = rsqrtf(red[0] * h);
    }

    int tid = blockIdx.x * blockDim.x + threadIdx.x;
    if (tid >= FB_TOT) return;
    const float INV_S3 = 0.57735026918962576f;
    const float WSCALE = 0.125f * 0.125f * 0.17677669529663687f;

    int mbase, N;
    if (tid < FB_SM)           { mbase = (tid / 2048) * 2048; N = 32; }
    else if (tid < FB_WM2)     { mbase = FB_WM1; N = 64; }
    else if (tid < FB_WM3)     { mbase = FB_WM2; N = 64; }
    else                       { mbase = FB_WM3; N = 128; }
    int idx = tid - mbase;
    int g = idx >> 6, pos = idx & 63, l = pos >> 1, hh = pos & 1;
    int ntn = N >> 3, k8 = g / ntn, n8 = g % ntn;
    int row = k8 * 8 + (l & 3) + 4 * hh;   // K index
    int col = n8 * 8 + (l >> 2);           // N index

    float v;
    if (tid < 2048)            v = w0[row * 32 + col];
    else if (tid < 4096)       v = w1[row * 32 + col] * INV_S3;
    else if (tid < 6144)       v = w2[row * 32 + col];
    else if (tid < 8192)       v = w3[row * 32 + col];
    else if (tid < FB_SM) {
        const float* L = (tid < 10240) ? Wl0 : Wl1;
        const float* F = (tid < 10240) ? Wf0 : Wf1;
        float acc = 0.0f;
        for (int w = 0; w < 32; w++) acc = fmaf(L[row * 32 + w], F[w * 32 + col], acc);
        v = acc * WSCALE;
    }
    else if (tid < FB_WM2)     v = Wm1[row * 64 + col] * 0.125f;
    else if (tid < FB_WM3)     v = Wm2[row * 64 + col] * 0.125f;
    else                       v = Wm3[row * 128 + col] * 0.125f;
    g_wbuf[tid] = __uint_as_float(tf32(v));
}

// ---------------- main ----------------
__global__ __launch_bounds__(32 * NWARP, 1)
void tp_mma_kernel(const float* __restrict__ x1a, const float* __restrict__ x1b,
                   const float4* __restrict__ x2, const float* __restrict__ scalars,
                   float* __restrict__ out, int nrows) {
    extern __shared__ float smem[];
    {
        const float4* src = (const float4*)g_wbuf;
        float4* dst = (float4*)smem;
        for (int i = threadIdx.x; i < FB_SM / 4; i += 32 * NWARP) dst[i] = src[i];
    }
    __syncthreads();
    const float cst = g_cst;
    const float* wm1g = g_wbuf + FB_WM1;
    const float* wm2g = g_wbuf + FB_WM2;
    const float* wm3g = g_wbuf + FB_WM3;

    const int lane = threadIdx.x & 31, wid = threadIdx.x >> 5;
    const int r4 = lane >> 2, m4 = lane & 3;

    float* A0 = smem + FB_SM + wid * ARENA;
    float* A1 = A0 + TFL;
    float* A2 = A1 + TFL;
    float* A3 = A2 + TFL;

    const int gw = blockIdx.x * NWARP + wid, gwn = gridDim.x * NWARP;
    const int ntiles = nrows >> 4;

    for (int t = gw; t < ntiles; t += gwn) {
        const int base = t * 16;

        // ---- stage scalars (fp32) ----
#pragma unroll
        for (int j = 0; j < 8; j++) {
            int row = r4 + 8 * (j & 1), f4 = m4 + 4 * (j >> 1);
            *(float4*)&A0[row * TSTR + 4 * f4] =
                ((const float4*)scalars)[(base + row) * 16 + f4];
        }
        __syncwarp();

        // ---- MLP GEMM1 -> silu -> GEMM2 -> silu -> GEMM3 (weights via L2) ----
        float h[32];
#pragma unroll
        for (int i = 0; i < 32; i++) h[i] = 0.f;
        gemm16g<8>(h, A0, wm1g, r4, m4, lane);
        __syncwarp();
#pragma unroll
        for (int nt = 0; nt < 8; nt++) {
            float a = h[4 * nt],     b = h[4 * nt + 1];
            float c = h[4 * nt + 2], d = h[4 * nt + 3];
            float2 lo = {cst * a / (1.f + __expf(-a)), cst * b / (1.f + __expf(-b))};
            float2 hi = {cst * c / (1.f + __expf(-c)), cst * d / (1.f + __expf(-d))};
            *(float2*)&A0[r4 * TSTR + nt * 8 + 2 * m4]       = lo;
            *(float2*)&A0[(r4 + 8) * TSTR + nt * 8 + 2 * m4] = hi;
        }
        __syncwarp();
#pragma unroll
        for (int i = 0; i < 32; i++) h[i] = 0.f;
        gemm16g<8>(h, A0, wm2g, r4, m4, lane);
        __syncwarp();
#pragma unroll
        for (int nt = 0; nt < 8; nt++) {
            float a = h[4 * nt],     b = h[4 * nt + 1];
            float c = h[4 * nt + 2], d = h[4 * nt + 3];
            float2 lo = {cst * a / (1.f + __expf(-a)), cst * b / (1.f + __expf(-b))};
            float2 hi = {cst * c / (1.f + __expf(-c)), cst * d / (1.f + __expf(-d))};
            *(float2*)&A0[r4 * TSTR + nt * 8 + 2 * m4]       = lo;
            *(float2*)&A0[(r4 + 8) * TSTR + nt * 8 + 2 * m4] = hi;
        }
        __syncwarp();
        float wt[64];
#pragma unroll
        for (int i = 0; i < 64; i++) wt[i] = 0.f;
        gemm16g<16>(wt, A0, wm3g, r4, m4, lane);
        __syncwarp();

        // ---- stage x1: head -> s0 (A0), tail -> s1 planes (A1..A3), all float4 ----
        // head: s0[row][arr*32 + 4j..] = x1{a,b}[row][4j..4j+3]
#pragma unroll
        for (int it = 0; it < 8; it++) {
            int fid = it * 32 + lane;
            int row = fid >> 4, within = fid & 15;
            int arr = within >> 3, j = within & 7;
            const float4* src = arr ? (const float4*)x1b : (const float4*)x1a;
            float4 v = src[(base + row) * 32 + j];
            *(float4*)&A0[row * TSTR + arr * 32 + 4 * j] = v;
        }
        // tail: 12 consecutive floats = 4 (u,k)-triples -> one float4 per k-plane
#pragma unroll
        for (int it = 0; it < 8; it++) {
            int sid = it * 32 + lane;
            int row = sid >> 4, within = sid & 15;
            int arr = within >> 3, q = within & 7;
            const float4* src = arr ? (const float4*)x1b : (const float4*)x1a;
            int p = (base + row) * 32 + 8 + 3 * q;
            float4 v0 = src[p], v1 = src[p + 1], v2 = src[p + 2];
            int off = row * TSTR + arr * 32 + 4 * q;
            *(float4*)&A1[off] = make_float4(v0.x, v0.w, v1.z, v2.y);
            *(float4*)&A2[off] = make_float4(v0.y, v1.x, v1.w, v2.z);
            *(float4*)&A3[off] = make_float4(v0.z, v1.y, v2.x, v2.w);
        }
        __syncwarp();

        // ---- y direct from global (L1-hot) ----
        float4 yA = __ldg(&x2[base + r4]);
        float4 yB = __ldg(&x2[base + r4 + 8]);
        const float y0A = yA.x, yA1 = yA.y, yA2 = yA.z, yA3 = yA.w;
        const float y0B = yB.x, yB1 = yB.y, yB2 = yB.z, yB3 = yB.w;

        // ---- G4/G5: R0 = s0@w0, Pp = s0@w2 (shared A frags) ----
        float R0[16], Pp[16], R1[16];
#pragma unroll
        for (int i = 0; i < 16; i++) { R0[i] = 0.f; Pp[i] = 0.f; R1[i] = 0.f; }
#pragma unroll
        for (int k8 = 0; k8 < 8; k8++) {
            const float* ap = A0 + r4 * TSTR + k8 * 8 + m4;
            u32 a0 = tf32(ap[0]);
            u32 a1 = tf32(ap[8 * TSTR]);
            u32 a2 = tf32(ap[4]);
            u32 a3 = tf32(ap[8 * TSTR + 4]);
            const float* w0p = smem + FB_W0 + k8 * 4 * 64 + 2 * lane;
            const float* w2p = smem + FB_W2 + k8 * 4 * 64 + 2 * lane;
#pragma unroll
            for (int nt = 0; nt < 4; nt++) {
                uint2 b0 = *(const uint2*)(w0p + nt * 64);
                mma_t(R0 + 4 * nt, a0, a1, a2, a3, b0.x, b0.y);
                uint2 b2 = *(const uint2*)(w2p + nt * 64);
                mma_t(Pp + 4 * nt, a0, a1, a2, a3, b2.x, b2.y);
            }
        }

        // ---- G6: R1 = t1@w1, t1 frags built on the fly ----
#pragma unroll
        for (int k8 = 0; k8 < 8; k8++) {
            int o = r4 * TSTR + k8 * 8 + m4;
            float t0  = A1[o] * yA1 + A2[o] * yA2 + A3[o] * yA3;
            float t2  = A1[o + 4] * yA1 + A2[o + 4] * yA2 + A3[o + 4] * yA3;
            float t1v = A1[o + 8 * TSTR] * yB1 + A2[o + 8 * TSTR] * yB2 + A3[o + 8 * TSTR] * yB3;
            float t3  = A1[o + 8 * TSTR + 4] * yB1 + A2[o + 8 * TSTR + 4] * yB2 + A3[o + 8 * TSTR + 4] * yB3;
            u32 a0 = tf32(t0), a1 = tf32(t1v), a2 = tf32(t2), a3 = tf32(t3);
            const float* w1p = smem + FB_W1 + k8 * 4 * 64 + 2 * lane;
#pragma unroll
            for (int nt = 0; nt < 4; nt++) {
                uint2 b = *(const uint2*)(w1p + nt * 64);
                mma_t(R1 + 4 * nt, a0, a1, a2, a3, b.x, b.y);
            }
        }
        __syncwarp();   // s0 reads done -> overlay m0 on A0

        // ---- m0 build -> A0 (float2 stores) ----
#pragma unroll
        for (int nt = 0; nt < 4; nt++) {
            int u = nt * 8 + 2 * m4;
            *(float2*)&A0[r4 * TSTR + u] =
                make_float2(y0A * R0[4 * nt] * wt[4 * nt], y0A * R0[4 * nt + 1] * wt[4 * nt + 1]);
            *(float2*)&A0[(r4 + 8) * TSTR + u] =
                make_float2(y0B * R0[4 * nt + 2] * wt[4 * nt + 2], y0B * R0[4 * nt + 3] * wt[4 * nt + 3]);
            int wi = 4 * (nt + 4);
            *(float2*)&A0[r4 * TSTR + 32 + u] =
                make_float2(R1[4 * nt] * wt[wi], R1[4 * nt + 1] * wt[wi + 1]);
            *(float2*)&A0[(r4 + 8) * TSTR + 32 + u] =
                make_float2(R1[4 * nt + 2] * wt[wi + 2], R1[4 * nt + 3] * wt[wi + 3]);
        }

        // ---- G7: Qk = s1k@w3 (B shared across k) ----
        float Q[48];
#pragma unroll
        for (int i = 0; i < 48; i++) Q[i] = 0.f;
#pragma unroll
        for (int k8 = 0; k8 < 8; k8++) {
            u32 A[3][4];
#pragma unroll
            for (int k = 0; k < 3; k++) {
                const float* Tk = (k == 0) ? A1 : ((k == 1) ? A2 : A3);
                int o = r4 * TSTR + k8 * 8 + m4;
                A[k][0] = tf32(Tk[o]);
                A[k][1] = tf32(Tk[o + 8 * TSTR]);
                A[k][2] = tf32(Tk[o + 4]);
                A[k][3] = tf32(Tk[o + 8 * TSTR + 4]);
            }
            const float* w3p = smem + FB_W3 + k8 * 4 * 64 + 2 * lane;
#pragma unroll
            for (int nt = 0; nt < 4; nt++) {
                uint2 b = *(const uint2*)(w3p + nt * 64);
#pragma unroll
                for (int k = 0; k < 3; k++)
                    mma_t(Q + 16 * k + 4 * nt, A[k][0], A[k][1], A[k][2], A[k][3], b.x, b.y);
            }
        }
        __syncwarp();   // s1 reads done -> overlay m1k

        // ---- m1k build -> A1..A3 (float2 stores) ----
#pragma unroll
        for (int k = 0; k < 3; k++) {
            float* Tk = (k == 0) ? A1 : ((k == 1) ? A2 : A3);
            float ykA = (k == 0) ? yA1 : ((k == 1) ? yA2 : yA3);
            float ykB = (k == 0) ? yB1 : ((k == 1) ? yB2 : yB3);
#pragma unroll
            for (int nt = 0; nt < 4; nt++) {
                int wi = 4 * (nt + 8), wj = 4 * (nt + 12);
                int u = nt * 8 + 2 * m4;
                *(float2*)&Tk[r4 * TSTR + u] =
                    make_float2(ykA * Pp[4 * nt] * wt[wi], ykA * Pp[4 * nt + 1] * wt[wi + 1]);
                *(float2*)&Tk[(r4 + 8) * TSTR + u] =
                    make_float2(ykB * Pp[4 * nt + 2] * wt[wi + 2], ykB * Pp[4 * nt + 3] * wt[wi + 3]);
                *(float2*)&Tk[r4 * TSTR + 32 + u] =
                    make_float2(y0A * Q[16 * k + 4 * nt] * wt[wj], y0A * Q[16 * k + 4 * nt + 1] * wt[wj + 1]);
                *(float2*)&Tk[(r4 + 8) * TSTR + 32 + u] =
                    make_float2(y0B * Q[16 * k + 4 * nt + 2] * wt[wj + 2], y0B * Q[16 * k + 4 * nt + 3] * wt[wj + 3]);
            }
        }
        __syncwarp();

        // ---- G8: O0 = m0@WA ; G9: Ok = m1k@WB (B shared) ----
        float O0[16];
#pragma unroll
        for (int i = 0; i < 16; i++) O0[i] = 0.f;
        gemm16s<4>(O0, A0, smem + FB_WA, r4, m4, lane);

        float O[48];
#pragma unroll
        for (int i = 0; i < 48; i++) O[i] = 0.f;
#pragma unroll
        for (int k8 = 0; k8 < 8; k8++) {
            u32 A[3][4];
#pragma unroll
            for (int k = 0; k < 3; k++) {
                const float* Tk = (k == 0) ? A1 : ((k == 1) ? A2 : A3);
                int o = r4 * TSTR + k8 * 8 + m4;
                A[k][0] = tf32(Tk[o]);
                A[k][1] = tf32(Tk[o + 8 * TSTR]);
                A[k][2] = tf32(Tk[o + 4]);
                A[k][3] = tf32(Tk[o + 8 * TSTR + 4]);
            }
            const float* wbp = smem + FB_WB + k8 * 4 * 64 + 2 * lane;
#pragma unroll
            for (int nt = 0; nt < 4; nt++) {
                uint2 b = *(const uint2*)(wbp + nt * 64);
#pragma unroll
                for (int k = 0; k < 3; k++)
                    mma_t(O + 16 * k + 4 * nt, A[k][0], A[k][1], A[k][2], A[k][3], b.x, b.y);
            }
        }
        __syncwarp();   // m reads done -> overlay out staging on A0/A1

        // ---- stage outputs (OB = A0, stride OSTR) ----
        float* OB = A0;
#pragma unroll
        for (int nt = 0; nt < 4; nt++) {
            int u = nt * 8 + 2 * m4;
            *(float2*)&OB[r4 * OSTR + u]       = make_float2(O0[4 * nt],     O0[4 * nt + 1]);
            *(float2*)&OB[(r4 + 8) * OSTR + u] = make_float2(O0[4 * nt + 2], O0[4 * nt + 3]);
#pragma unroll
            for (int k = 0; k < 3; k++) {
                int c = 32 + 3 * u + k;
                OB[r4 * OSTR + c]           = O[16 * k + 4 * nt];
                OB[r4 * OSTR + c + 3]       = O[16 * k + 4 * nt + 1];
                OB[(r4 + 8) * OSTR + c]     = O[16 * k + 4 * nt + 2];
                OB[(r4 + 8) * OSTR + c + 3] = O[16 * k + 4 * nt + 3];
            }
        }
        __syncwarp();
#pragma unroll
        for (int rr = 0; rr < 16; rr++)
            ((float4*)out)[(base + rr) * 32 + lane] = *(const float4*)&OB[rr * OSTR + 4 * lane];
        __syncwarp();
    }
}

// ---------------- launch ----------------
extern "C" void kernel_launch(void* const* d_in, const int* in_sizes, int n_in,
                              void* d_out, int out_size) {
    const float* x1a     = (const float*)d_in[0];
    const float* x1b     = (const float*)d_in[1];
    const float* x2      = (const float*)d_in[2];
    const float* scalars = (const float*)d_in[3];
    const float* w0      = (const float*)d_in[4];
    const float* w1      = (const float*)d_in[5];
    const float* w2      = (const float*)d_in[6];
    const float* w3      = (const float*)d_in[7];
    const float* Wl0     = (const float*)d_in[8];
    const float* Wl1     = (const float*)d_in[9];
    const float* Wm1     = (const float*)d_in[10];
    const float* Wm2     = (const float*)d_in[11];
    const float* Wm3     = (const float*)d_in[12];
    const float* Wf0     = (const float*)d_in[13];
    const float* Wf1     = (const float*)d_in[14];
    int n = in_sizes[0] / 128;

    cudaFuncSetAttribute(tp_mma_kernel, cudaFuncAttributeMaxDynamicSharedMemorySize, SMEM_BYTES);

    prep_kernel<<<112, 256>>>(w0, w1, w2, w3, Wl0, Wl1, Wm1, Wm2, Wm3, Wf0, Wf1);
    tp_mma_kernel<<<148, 32 * NWARP, SMEM_BYTES>>>(x1a, x1b, (const float4*)x2, scalars,
                                                   (float*)d_out, n);
}